// round 15
// baseline (speedup 1.0000x reference)
#include <cuda_runtime.h>
#include <math.h>

#define N_NODES      100000
#define HIDDEN       256
#define K_CLUSTERS   20
#define CLUSTER_SIZE 5000

// Pass-1 grid
#define P1_BPC   50
#define P1_ROWS  (CLUSTER_SIZE / P1_BPC)   // 100
#define NGROUPS  4                          // 4 groups x 64 threads
#define P1_DEPTH 6                          // cp.async pipeline depth (stages of 4 rows)
#define P1_NST   (P1_ROWS / 4)              // 25 stages

// Scores grid (measured best: 2 waves at ~3 blocks/SM)
#define SC_BPC  40
#define SC_ROWS (CLUSTER_SIZE / SC_BPC)    // 125
#define NWARPS  8

// Scratch (allocation-free rule: __device__ globals).
__device__ float g_partial[K_CLUSTERS * P1_BPC * HIDDEN]; // ~1 MB
__device__ float g_wc[K_CLUSTERS * HIDDEN];

__device__ __forceinline__ float softplus_f(float x) {
    return fmaxf(x, 0.0f) + log1pf(__expf(-fabsf(x)));
}

__device__ __forceinline__ void add4(float4& a, const float4 v) {
    a.x += v.x; a.y += v.y; a.z += v.z; a.w += v.w;
}

__device__ __forceinline__ unsigned int smem_u32(const void* p) {
    return (unsigned int)__cvta_generic_to_shared(p);
}
#define CP_ASYNC16(dst, src) \
    asm volatile("cp.async.cg.shared.global [%0], [%1], 16;" :: "r"(dst), "l"(src))
#define CP_COMMIT() asm volatile("cp.async.commit_group;")
#define CP_WAIT(n)  asm volatile("cp.async.wait_group %0;" :: "n"(n))

// Pass 1: per-(cluster, block) partial column sums of gathered h1 rows.
// cp.async pipeline: stage = 4 rows (4KB); thread t copies 16B of row (t/64)
// at float4-col (t&63), and later consumes EXACTLY the bytes it copied ->
// no __syncthreads in the loop; data MLP lives in smem, not registers.
__global__ void __launch_bounds__(HIDDEN)
k_partial_sum(const float* __restrict__ h1, const int* __restrict__ ci) {
    const int k  = blockIdx.y;
    const int b  = blockIdx.x;
    const int t  = threadIdx.x;
    const int g  = t >> 6;          // group / row-within-stage 0..3
    const int c4 = t & 63;          // float4 column 0..63

    __shared__ __align__(16) float4 buf[P1_DEPTH][NGROUPS][HIDDEN / 4]; // 24 KB
    __shared__ int s_idx[P1_ROWS];
    __shared__ __align__(16) float4 red[NGROUPS][HIDDEN / 4];           // 4 KB

    if (t < P1_ROWS) s_idx[t] = ci[k * CLUSTER_SIZE + b * P1_ROWS + t];
    __syncthreads();

    float4 acc = make_float4(0.f, 0.f, 0.f, 0.f);

    // Prologue: fill the pipeline (one group commit per stage).
    #pragma unroll
    for (int s = 0; s < P1_DEPTH; ++s) {
        long long row = (long long)s_idx[s * NGROUPS + g];
        CP_ASYNC16(smem_u32(&buf[s][g][c4]), h1 + row * HIDDEN + c4 * 4);
        CP_COMMIT();
    }

    // Main loop: wait oldest, consume own slice, refill slot (or empty commit
    // in the tail so wait_group accounting stays uniform).
    for (int s = 0; s < P1_NST; ++s) {
        CP_WAIT(P1_DEPTH - 1);                 // stage s complete (per-thread)
        const int slot = s % P1_DEPTH;
        add4(acc, buf[slot][g][c4]);
        const int s2 = s + P1_DEPTH;
        if (s2 < P1_NST) {
            long long row = (long long)s_idx[s2 * NGROUPS + g];
            CP_ASYNC16(smem_u32(&buf[slot][g][c4]), h1 + row * HIDDEN + c4 * 4);
        }
        CP_COMMIT();
    }

    // Combine the 4 groups' column partials via smem.
    red[g][c4] = acc;
    __syncthreads();

    const float* redf = reinterpret_cast<const float*>(red);
    float s = redf[0 * HIDDEN + t] + redf[1 * HIDDEN + t]
            + redf[2 * HIDDEN + t] + redf[3 * HIDDEN + t];
    g_partial[(k * P1_BPC + b) * HIDDEN + t] = s;
}

// Pass 2: reduce partials -> mean -> sigmoid -> c; Wc = W @ c. One block per
// cluster. Also zeroes out[0] (poisoned by harness) before pass 3 runs.
__global__ void __launch_bounds__(HIDDEN)
k_make_wc(const float* __restrict__ W, float* __restrict__ out) {
    const int k = blockIdx.x;
    const int d = threadIdx.x;
    __shared__ __align__(16) float c_s[HIDDEN];

    float s = 0.0f;
    #pragma unroll
    for (int b = 0; b < P1_BPC; ++b)
        s += g_partial[(k * P1_BPC + b) * HIDDEN + d];

    float m = s * (1.0f / (float)CLUSTER_SIZE);
    c_s[d] = 1.0f / (1.0f + __expf(-m));       // sigmoid
    __syncthreads();

    const float4* Wr = reinterpret_cast<const float4*>(W + (long long)d * HIDDEN);
    const float4* c4 = reinterpret_cast<const float4*>(c_s);
    float wc = 0.0f;
    #pragma unroll 8
    for (int e = 0; e < HIDDEN / 4; ++e) {
        float4 w4 = Wr[e];
        float4 cc = c4[e];
        wc += w4.x * cc.x + w4.y * cc.y + w4.z * cc.z + w4.w * cc.w;
    }
    g_wc[k * HIDDEN + d] = wc;

    if (k == 0 && d == 0) out[0] = 0.0f;   // runs before k_scores (stream order)
}

// Pass 3: per-row bilinear scores + softplus; warp per row, 2 rows in flight
// per warp iteration for MLP. Each block atomicAdds its pre-scaled sum into out.
__global__ void __launch_bounds__(HIDDEN)
k_scores(const float* __restrict__ h1, const float* __restrict__ h2,
         const int* __restrict__ ci, const float* __restrict__ bptr,
         float* __restrict__ out) {
    const int k    = blockIdx.y;
    const int blk  = blockIdx.x;
    const int tid  = threadIdx.x;
    const int w    = tid >> 5;
    const int lane = tid & 31;

    __shared__ __align__(16) float wc_s[HIDDEN];
    __shared__ float warp_acc[NWARPS];

    wc_s[tid] = g_wc[k * HIDDEN + tid];
    __syncthreads();

    const float bb = *bptr;
    const float4* wc4 = reinterpret_cast<const float4*>(wc_s);
    const float4 wa = wc4[lane];
    const float4 wb = wc4[lane + 32];

    const int* idx = ci + k * CLUSTER_SIZE + blk * SC_ROWS;

    float acc = 0.0f;
    for (int n = w; n < SC_ROWS; n += 2 * NWARPS) {
        const int n2 = n + NWARPS;
        const bool has2 = (n2 < SC_ROWS);

        long long rA = (long long)idx[n];
        long long rB = has2 ? (long long)idx[n2] : rA;

        const float4* p1A = reinterpret_cast<const float4*>(h1 + rA * HIDDEN);
        const float4* p2A = reinterpret_cast<const float4*>(h2 + rA * HIDDEN);
        const float4* p1B = reinterpret_cast<const float4*>(h1 + rB * HIDDEN);
        const float4* p2B = reinterpret_cast<const float4*>(h2 + rB * HIDDEN);

        float4 a0 = p1A[lane], a1 = p1A[lane + 32];
        float4 b0 = p2A[lane], b1 = p2A[lane + 32];
        float4 c0 = p1B[lane], c1 = p1B[lane + 32];
        float4 e0 = p2B[lane], e1 = p2B[lane + 32];

        float s1A = a0.x*wa.x + a0.y*wa.y + a0.z*wa.z + a0.w*wa.w
                  + a1.x*wb.x + a1.y*wb.y + a1.z*wb.z + a1.w*wb.w;
        float s2A = b0.x*wa.x + b0.y*wa.y + b0.z*wa.z + b0.w*wa.w
                  + b1.x*wb.x + b1.y*wb.y + b1.z*wb.z + b1.w*wb.w;
        float s1B = c0.x*wa.x + c0.y*wa.y + c0.z*wa.z + c0.w*wa.w
                  + c1.x*wb.x + c1.y*wb.y + c1.z*wb.z + c1.w*wb.w;
        float s2B = e0.x*wa.x + e0.y*wa.y + e0.z*wa.z + e0.w*wa.w
                  + e1.x*wb.x + e1.y*wb.y + e1.z*wb.z + e1.w*wb.w;

        #pragma unroll
        for (int o = 16; o > 0; o >>= 1) {
            s1A += __shfl_xor_sync(0xFFFFFFFFu, s1A, o);
            s2A += __shfl_xor_sync(0xFFFFFFFFu, s2A, o);
            s1B += __shfl_xor_sync(0xFFFFFFFFu, s1B, o);
            s2B += __shfl_xor_sync(0xFFFFFFFFu, s2B, o);
        }
        acc += softplus_f(-(s1A + bb)) + softplus_f(s2A + bb);
        if (has2)
            acc += softplus_f(-(s1B + bb)) + softplus_f(s2B + bb);
    }

    if (lane == 0) warp_acc[w] = acc;
    __syncthreads();
    if (tid == 0) {
        float t = 0.0f;
        #pragma unroll
        for (int i = 0; i < NWARPS; ++i) t += warp_acc[i];
        atomicAdd(out, t * (0.5f / (float)(K_CLUSTERS * CLUSTER_SIZE)));
    }
}

extern "C" void kernel_launch(void* const* d_in, const int* in_sizes, int n_in,
                              void* d_out, int out_size) {
    const float* h1 = (const float*)d_in[0];
    const float* h2 = (const float*)d_in[1];
    const int*   ci = (const int*)d_in[2];
    const float* W  = (const float*)d_in[3];
    const float* b  = (const float*)d_in[4];
    float* out = (float*)d_out;

    dim3 grid1(P1_BPC, K_CLUSTERS);
    dim3 grid3(SC_BPC, K_CLUSTERS);
    k_partial_sum<<<grid1, HIDDEN>>>(h1, ci);
    k_make_wc<<<K_CLUSTERS, HIDDEN>>>(W, out);
    k_scores<<<grid3, HIDDEN>>>(h1, h2, ci, b, out);
}